// round 3
// baseline (speedup 1.0000x reference)
#include <cuda_runtime.h>

// ---------------------------------------------------------------------------
// GMMNet, 4 pixels per thread: two packed-f32x2 streams sharing each weight
// load (1 LDCU + 2 FFMA2 per weight = 3 issues / 4 MACs).
// NPIX/4 == H*W, so thread `hw` handles pixel hw of batches {0,1} (stream 0)
// and {2,3} (stream 1).
// Carried state per stream: pi[5], mu[15], r2[5]=1/sigma^2, cf[5]=C0/sigma^3.
// ---------------------------------------------------------------------------

typedef unsigned long long u64;

namespace {
constexpr int Bn = 4, Sn = 8, Cn = 3, Hn = 384, Wn = 384, Kn = 5, CKn = 15;
constexpr int HWn  = Hn * Wn;            // 147456 (= threads launched)

// constant-bank layout (element offsets, ascending)
constexpr int PI_W1 = 0,   PI_B1 = 50,  PI_W2 = 55,  PI_B2 = 80;
constexpr int MU_W1 = 85,  MU_B1 = 430, MU_W2 = 445, MU_B2 = 670;
constexpr int SG_W1 = 685, SG_B1 = 800, SG_W2 = 805, SG_B2 = 830;
constexpr int GA_W1 = 835, GA_B1 = 860, GA_W2 = 865, GA_B2 = 870;
constexpr int NWTS  = 871;
}

__constant__ u64 cw2[NWTS];          // duplicated {w,w} pairs
__device__   u64 g_staging[NWTS];    // staging for capturable copy-to-constant

// ---- packed f32x2 helpers --------------------------------------------------
__device__ __forceinline__ u64 pk(float lo, float hi) {
    u64 r; asm("mov.b64 %0, {%1, %2};" : "=l"(r) : "f"(lo), "f"(hi)); return r;
}
__device__ __forceinline__ void upk(u64 v, float& lo, float& hi) {
    asm("mov.b64 {%0, %1}, %2;" : "=f"(lo), "=f"(hi) : "l"(v));
}
__device__ __forceinline__ u64 fma2(u64 a, u64 b, u64 c) {
    u64 d; asm("fma.rn.f32x2 %0, %1, %2, %3;" : "=l"(d) : "l"(a), "l"(b), "l"(c)); return d;
}
__device__ __forceinline__ u64 mul2(u64 a, u64 b) {
    u64 d; asm("mul.rn.f32x2 %0, %1, %2;" : "=l"(d) : "l"(a), "l"(b)); return d;
}
__device__ __forceinline__ u64 add2(u64 a, u64 b) {
    u64 d; asm("add.rn.f32x2 %0, %1, %2;" : "=l"(d) : "l"(a), "l"(b)); return d;
}
__device__ __forceinline__ float ex2f(float x) {
    float y; asm("ex2.approx.f32 %0, %1;" : "=f"(y) : "f"(x)); return y;
}
__device__ __forceinline__ float rcpf(float x) {
    float y; asm("rcp.approx.f32 %0, %1;" : "=f"(y) : "f"(x)); return y;
}
__device__ __forceinline__ u64 ex2_2(u64 x) {
    float lo, hi; upk(x, lo, hi); return pk(ex2f(lo), ex2f(hi));
}
__device__ __forceinline__ u64 rcp_2(u64 x) {
    float lo, hi; upk(x, lo, hi); return pk(rcpf(lo), rcpf(hi));
}
// exact relu: 0.5*(x + |x|)
__device__ __forceinline__ u64 relu2(u64 x) {
    const u64 ax = x & 0x7fffffff7fffffffULL;
    return mul2(add2(x, ax), 0x3f0000003f000000ULL /* {0.5f,0.5f} */);
}

// ---- weight duplication kernel ----------------------------------------------
struct WPtrs { const float* p[16]; };

__global__ void dup_weights(WPtrs w) {
    const int i = blockIdx.x * blockDim.x + threadIdx.x;
    if (i >= NWTS) return;
    constexpr int off[17] = {PI_W1, PI_B1, PI_W2, PI_B2,
                             MU_W1, MU_B1, MU_W2, MU_B2,
                             SG_W1, SG_B1, SG_W2, SG_B2,
                             GA_W1, GA_B1, GA_W2, GA_B2, NWTS};
    int s = 0;
#pragma unroll
    for (int k = 1; k < 16; k++) if (i >= off[k]) s = k;
    const float v = w.p[s][i - off[s]];
    g_staging[i] = pk(v, v);
}

// ---- main kernel -------------------------------------------------------------
__global__ void __launch_bounds__(256)
gmm4_kernel(const float* __restrict__ frames,   // [B,S,C,H,W]
            const float* __restrict__ mu0,      // [B,CK,H,W]
            float* __restrict__ out)            // [B,S,1,H,W]
{
    const int hw = blockIdx.x * blockDim.x + threadIdx.x;
    if (hw >= HWn) return;

    const float L2E = 1.4426950408889634f;
    const u64 LOG2E2 = pk(L2E, L2E);
    const u64 NL2E2  = pk(-L2E, -L2E);
    const u64 NHL2E2 = pk(-0.7213475204444817f, -0.7213475204444817f); // -0.5*log2e
    const u64 ONE2   = pk(1.0f, 1.0f);
    const u64 NEG12  = pk(-1.0f, -1.0f);
    const u64 C02    = pk(0.06349363593424097f, 0.06349363593424097f); // (2pi)^-1.5

    // carried state: stream j covers batches (2j, 2j+1)
    u64 pi[2][Kn], mu[2][CKn], r2[2][Kn], cf[2][Kn];
#pragma unroll
    for (int j = 0; j < 2; j++)
#pragma unroll
        for (int k = 0; k < Kn; k++) {
            pi[j][k] = pk(0.2f, 0.2f);
            r2[j][k] = ONE2;          // (1/sigma)^2, sigma0=1
            cf[j][k] = C02;           // C0*(1/sigma)^3
        }
#pragma unroll
    for (int j = 0; j < 2; j++)
#pragma unroll
        for (int i = 0; i < CKn; i++)
            mu[j][i] = pk(mu0[((2 * j)     * CKn + i) * HWn + hw],
                          mu0[((2 * j + 1) * CKn + i) * HWn + hw]);

    const float* fbase = frames + hw;
    float*       obase = out + hw;

    for (int s = 0; s < Sn; s++) {
        u64 x[2][Cn];
#pragma unroll
        for (int j = 0; j < 2; j++)
#pragma unroll
            for (int c = 0; c < Cn; c++)
                x[j][c] = pk(fbase[(((2*j)   * Sn + s) * Cn + c) * HWn],
                             fbase[(((2*j+1) * Sn + s) * Cn + c) * HWn]);

        // ---- density 1, alpha, rho ---------------------------------------
        u64 alpha[2][Kn], rho[2][Kn];
#pragma unroll
        for (int k = 0; k < Kn; k++)
#pragma unroll
            for (int j = 0; j < 2; j++) {
                u64 t0 = fma2(mu[j][k*Cn+0], NEG12, x[j][0]);
                u64 d  = mul2(t0, t0);
                u64 t1 = fma2(mu[j][k*Cn+1], NEG12, x[j][1]);
                d = fma2(t1, t1, d);
                u64 t2 = fma2(mu[j][k*Cn+2], NEG12, x[j][2]);
                d = fma2(t2, t2, d);
                const u64 e    = ex2_2(mul2(mul2(d, r2[j][k]), NHL2E2));
                const u64 dens = mul2(cf[j][k], e);
                alpha[j][k] = mul2(pi[j][k], dens);
                rho[j][k]   = mul2(alpha[j][k], dens);
            }

        // ---- pi MLP: [pi(5), alpha(5)] -> 5 relu -> 5, softmax ------------
        u64 hp[2][Kn];
#pragma unroll
        for (int o = 0; o < Kn; o++) {
            u64 a0 = cw2[PI_B1 + o], a1 = a0;
#pragma unroll
            for (int i = 0; i < Kn; i++) {
                const u64 w = cw2[PI_W1 + o * 10 + i];
                a0 = fma2(w, pi[0][i], a0);
                a1 = fma2(w, pi[1][i], a1);
            }
#pragma unroll
            for (int i = 0; i < Kn; i++) {
                const u64 w = cw2[PI_W1 + o * 10 + 5 + i];
                a0 = fma2(w, alpha[0][i], a0);
                a1 = fma2(w, alpha[1][i], a1);
            }
            hp[0][o] = relu2(a0);
            hp[1][o] = relu2(a1);
        }
        u64 pin[2][Kn], esum[2] = {0ULL, 0ULL};
#pragma unroll
        for (int o = 0; o < Kn; o++) {
            u64 a0 = cw2[PI_B2 + o], a1 = a0;
#pragma unroll
            for (int i = 0; i < Kn; i++) {
                const u64 w = cw2[PI_W2 + o * 5 + i];
                a0 = fma2(w, hp[0][i], a0);
                a1 = fma2(w, hp[1][i], a1);
            }
            pin[0][o] = ex2_2(mul2(a0, LOG2E2));
            pin[1][o] = ex2_2(mul2(a1, LOG2E2));
            esum[0] = add2(esum[0], pin[0][o]);
            esum[1] = add2(esum[1], pin[1][o]);
        }
#pragma unroll
        for (int j = 0; j < 2; j++) {
            const u64 einv = rcp_2(esum[j]);
#pragma unroll
            for (int k = 0; k < Kn; k++) pin[j][k] = mul2(pin[j][k], einv);
        }

        // ---- mu MLP: [x(3), mu(15), rho(5)] -> 15 relu -> 15, sigmoid ----
        u64 hm[2][CKn];
#pragma unroll
        for (int o = 0; o < CKn; o++) {
            const int base = MU_W1 + o * 23;
            u64 a0 = cw2[MU_B1 + o], a1 = a0;
#pragma unroll
            for (int c = 0; c < Cn; c++) {
                const u64 w = cw2[base + c];
                a0 = fma2(w, x[0][c], a0);
                a1 = fma2(w, x[1][c], a1);
            }
#pragma unroll
            for (int i = 0; i < CKn; i++) {
                const u64 w = cw2[base + 3 + i];
                a0 = fma2(w, mu[0][i], a0);
                a1 = fma2(w, mu[1][i], a1);
            }
#pragma unroll
            for (int i = 0; i < Kn; i++) {
                const u64 w = cw2[base + 18 + i];
                a0 = fma2(w, rho[0][i], a0);
                a1 = fma2(w, rho[1][i], a1);
            }
            hm[0][o] = relu2(a0);
            hm[1][o] = relu2(a1);
        }
        u64 mun[2][CKn];
#pragma unroll
        for (int o = 0; o < CKn; o++) {
            u64 a0 = cw2[MU_B2 + o], a1 = a0;
#pragma unroll
            for (int i = 0; i < CKn; i++) {
                const u64 w = cw2[MU_W2 + o * 15 + i];
                a0 = fma2(w, hm[0][i], a0);
                a1 = fma2(w, hm[1][i], a1);
            }
            mun[0][o] = rcp_2(add2(ex2_2(mul2(a0, NL2E2)), ONE2));
            mun[1][o] = rcp_2(add2(ex2_2(mul2(a1, NL2E2)), ONE2));
        }

        // ---- sigma MLP: [x(3), mun(15), rho(5)] -> 5 relu -> 5 -----------
        u64 hs[2][Kn];
#pragma unroll
        for (int o = 0; o < Kn; o++) {
            const int base = SG_W1 + o * 23;
            u64 a0 = cw2[SG_B1 + o], a1 = a0;
#pragma unroll
            for (int c = 0; c < Cn; c++) {
                const u64 w = cw2[base + c];
                a0 = fma2(w, x[0][c], a0);
                a1 = fma2(w, x[1][c], a1);
            }
#pragma unroll
            for (int i = 0; i < CKn; i++) {
                const u64 w = cw2[base + 3 + i];
                a0 = fma2(w, mun[0][i], a0);
                a1 = fma2(w, mun[1][i], a1);
            }
#pragma unroll
            for (int i = 0; i < Kn; i++) {
                const u64 w = cw2[base + 18 + i];
                a0 = fma2(w, rho[0][i], a0);
                a1 = fma2(w, rho[1][i], a1);
            }
            hs[0][o] = relu2(a0);
            hs[1][o] = relu2(a1);
        }
#pragma unroll
        for (int o = 0; o < Kn; o++) {
            u64 a0 = cw2[SG_B2 + o], a1 = a0;
#pragma unroll
            for (int i = 0; i < Kn; i++) {
                const u64 w = cw2[SG_W2 + o * 5 + i];
                a0 = fma2(w, hs[0][i], a0);
                a1 = fma2(w, hs[1][i], a1);
            }
            // rinv = exp(-relu(a)); carry r2 = rinv^2, cf = C0*rinv^3
            const u64 r0 = ex2_2(mul2(relu2(a0), NL2E2));
            const u64 r1 = ex2_2(mul2(relu2(a1), NL2E2));
            r2[0][o] = mul2(r0, r0);
            r2[1][o] = mul2(r1, r1);
            cf[0][o] = mul2(mul2(r0, C02), r2[0][o]);
            cf[1][o] = mul2(mul2(r1, C02), r2[1][o]);
        }

        // ---- density 2, g = pi_new * dens2 --------------------------------
        u64 g[2][Kn];
#pragma unroll
        for (int k = 0; k < Kn; k++)
#pragma unroll
            for (int j = 0; j < 2; j++) {
                u64 t0 = fma2(mun[j][k*Cn+0], NEG12, x[j][0]);
                u64 d  = mul2(t0, t0);
                u64 t1 = fma2(mun[j][k*Cn+1], NEG12, x[j][1]);
                d = fma2(t1, t1, d);
                u64 t2 = fma2(mun[j][k*Cn+2], NEG12, x[j][2]);
                d = fma2(t2, t2, d);
                const u64 e = ex2_2(mul2(mul2(d, r2[j][k]), NHL2E2));
                g[j][k] = mul2(pin[j][k], mul2(cf[j][k], e));
            }

        // ---- gamma MLP: 5 -> 5 relu -> 1, sigmoid -------------------------
        u64 hg[2][Kn];
#pragma unroll
        for (int o = 0; o < Kn; o++) {
            u64 a0 = cw2[GA_B1 + o], a1 = a0;
#pragma unroll
            for (int i = 0; i < Kn; i++) {
                const u64 w = cw2[GA_W1 + o * 5 + i];
                a0 = fma2(w, g[0][i], a0);
                a1 = fma2(w, g[1][i], a1);
            }
            hg[0][o] = relu2(a0);
            hg[1][o] = relu2(a1);
        }
        u64 ga0 = cw2[GA_B2], ga1 = ga0;
#pragma unroll
        for (int i = 0; i < Kn; i++) {
            const u64 w = cw2[GA_W2 + i];
            ga0 = fma2(w, hg[0][i], ga0);
            ga1 = fma2(w, hg[1][i], ga1);
        }
        {
            const u64 s0 = rcp_2(add2(ex2_2(mul2(ga0, NL2E2)), ONE2));
            const u64 s1 = rcp_2(add2(ex2_2(mul2(ga1, NL2E2)), ONE2));
            float v0, v1, v2, v3;
            upk(s0, v0, v1);
            upk(s1, v2, v3);
            obase[(0 * Sn + s) * HWn] = v0;
            obase[(1 * Sn + s) * HWn] = v1;
            obase[(2 * Sn + s) * HWn] = v2;
            obase[(3 * Sn + s) * HWn] = v3;
        }

        // ---- carry ---------------------------------------------------------
#pragma unroll
        for (int j = 0; j < 2; j++) {
#pragma unroll
            for (int k = 0; k < Kn; k++)  pi[j][k] = pin[j][k];
#pragma unroll
            for (int i = 0; i < CKn; i++) mu[j][i] = mun[j][i];
        }
    }
}

extern "C" void kernel_launch(void* const* d_in, const int* in_sizes, int n_in,
                              void* d_out, int out_size)
{
    (void)in_sizes; (void)n_in; (void)out_size;
    const float* frames = (const float*)d_in[0];
    const float* mu0    = (const float*)d_in[2];   // d_in[1] = targets (unused)

    WPtrs w;
    for (int i = 0; i < 16; i++) w.p[i] = (const float*)d_in[3 + i];

    dup_weights<<<4, 256>>>(w);

    void* staging_addr = nullptr;
    cudaGetSymbolAddress(&staging_addr, g_staging);
    cudaMemcpyToSymbolAsync(cw2, staging_addr, NWTS * sizeof(u64), 0,
                            cudaMemcpyDeviceToDevice, 0);

    const int threads = 256;
    const int blocks  = HWn / threads;   // 576
    gmm4_kernel<<<blocks, threads>>>(frames, mu0, (float*)d_out);
}

// round 4
// speedup vs baseline: 1.3163x; 1.3163x over previous
#include <cuda_runtime.h>

// ---------------------------------------------------------------------------
// GMMNet, 2 pixels/thread, packed f32x2 (FFMA2). R4: log2e-folded weights,
// FMNMX-based relu (alu pipe), r2s-carried density exponent scale.
// ---------------------------------------------------------------------------

typedef unsigned long long u64;

namespace {
constexpr int Bn = 4, Sn = 8, Cn = 3, Hn = 384, Wn = 384, Kn = 5, CKn = 15;
constexpr int HWn  = Hn * Wn;            // 147456
constexpr int NPIX = Bn * HWn;           // 589824
constexpr int HALF = NPIX / 2;           // 294912

constexpr int PI_W1 = 0,   PI_B1 = 50,  PI_W2 = 55,  PI_B2 = 80;
constexpr int MU_W1 = 85,  MU_B1 = 430, MU_W2 = 445, MU_B2 = 670;
constexpr int SG_W1 = 685, SG_B1 = 800, SG_W2 = 805, SG_B2 = 830;
constexpr int GA_W1 = 835, GA_B1 = 860, GA_W2 = 865, GA_B2 = 870;
constexpr int NWTS  = 871;

constexpr float L2E  = 1.4426950408889634f;
}

__constant__ u64 cw2[NWTS];
__device__   u64 g_staging[NWTS];

// ---- packed helpers ---------------------------------------------------------
__device__ __forceinline__ u64 pk(float lo, float hi) {
    u64 r; asm("mov.b64 %0, {%1, %2};" : "=l"(r) : "f"(lo), "f"(hi)); return r;
}
__device__ __forceinline__ void upk(u64 v, float& lo, float& hi) {
    asm("mov.b64 {%0, %1}, %2;" : "=f"(lo), "=f"(hi) : "l"(v));
}
__device__ __forceinline__ u64 fma2(u64 a, u64 b, u64 c) {
    u64 d; asm("fma.rn.f32x2 %0, %1, %2, %3;" : "=l"(d) : "l"(a), "l"(b), "l"(c)); return d;
}
__device__ __forceinline__ u64 mul2(u64 a, u64 b) {
    u64 d; asm("mul.rn.f32x2 %0, %1, %2;" : "=l"(d) : "l"(a), "l"(b)); return d;
}
__device__ __forceinline__ u64 add2(u64 a, u64 b) {
    u64 d; asm("add.rn.f32x2 %0, %1, %2;" : "=l"(d) : "l"(a), "l"(b)); return d;
}
__device__ __forceinline__ float ex2f(float x) {
    float y; asm("ex2.approx.f32 %0, %1;" : "=f"(y) : "f"(x)); return y;
}
__device__ __forceinline__ float rcpf(float x) {
    float y; asm("rcp.approx.f32 %0, %1;" : "=f"(y) : "f"(x)); return y;
}
__device__ __forceinline__ u64 ex2_2(u64 x) {
    float lo, hi; upk(x, lo, hi); return pk(ex2f(lo), ex2f(hi));
}
__device__ __forceinline__ u64 rcp_2(u64 x) {
    float lo, hi; upk(x, lo, hi); return pk(rcpf(lo), rcpf(hi));
}
// relu / min-with-0 via scalar FMNMX on the register halves (alu pipe; the
// pack/unpack movs are register-pair aliasing and cost nothing)
__device__ __forceinline__ u64 relu2(u64 x) {
    float lo, hi; upk(x, lo, hi);
    return pk(fmaxf(lo, 0.f), fmaxf(hi, 0.f));
}
__device__ __forceinline__ u64 min0_2(u64 x) {
    float lo, hi; upk(x, lo, hi);
    return pk(fminf(lo, 0.f), fminf(hi, 0.f));
}

// ---- weight duplication + constant folding -----------------------------------
struct WPtrs { const float* p[16]; };

__global__ void dup_weights(WPtrs w) {
    const int i = blockIdx.x * blockDim.x + threadIdx.x;
    if (i >= NWTS) return;
    constexpr int off[17] = {PI_W1, PI_B1, PI_W2, PI_B2,
                             MU_W1, MU_B1, MU_W2, MU_B2,
                             SG_W1, SG_B1, SG_W2, SG_B2,
                             GA_W1, GA_B1, GA_W2, GA_B2, NWTS};
    int s = 0;
#pragma unroll
    for (int k = 1; k < 16; k++) if (i >= off[k]) s = k;
    float v = w.p[s][i - off[s]];
    // fold exp/sigmoid scales into second-layer weights+biases:
    //  pi  (softmax exp):   * log2e
    //  mu  (sigmoid):       * -log2e
    //  sg  (exp(-relu(a))): * -log2e   (relu(a)*-log2e == min(a',0))
    //  ga  (sigmoid):       * -log2e
    if (s == 2 || s == 3)                    v *=  L2E;   // PI_W2, PI_B2
    else if (s == 6 || s == 7)               v *= -L2E;   // MU_W2, MU_B2
    else if (s == 10 || s == 11)             v *= -L2E;   // SG_W2, SG_B2
    else if (s == 14 || s == 15)             v *= -L2E;   // GA_W2, GA_B2
    g_staging[i] = pk(v, v);
}

// ---- main kernel --------------------------------------------------------------
__global__ void __launch_bounds__(256)
gmm2_kernel(const float* __restrict__ frames,   // [B,S,C,H,W]
            const float* __restrict__ mu0,      // [B,CK,H,W]
            float* __restrict__ out)            // [B,S,1,H,W]
{
    const int t = blockIdx.x * blockDim.x + threadIdx.x;
    if (t >= HALF) return;

    const int b0 = t / HWn,  hw0 = t - b0 * HWn;
    const int p1 = t + HALF;
    const int b1 = p1 / HWn, hw1 = p1 - b1 * HWn;

    const float* f0 = frames + (b0 * Sn * Cn) * HWn + hw0;
    const float* f1 = frames + (b1 * Sn * Cn) * HWn + hw1;
    const float* m0 = mu0 + (b0 * CKn) * HWn + hw0;
    const float* m1 = mu0 + (b1 * CKn) * HWn + hw1;
    float* o0 = out + (b0 * Sn) * HWn + hw0;
    float* o1 = out + (b1 * Sn) * HWn + hw1;

    const u64 ONE2   = pk(1.0f, 1.0f);
    const u64 NEG12  = pk(-1.0f, -1.0f);
    const u64 C02    = pk(0.06349363593424097f, 0.06349363593424097f);   // (2pi)^-1.5
    const u64 NHL2E2 = pk(-0.7213475204444817f, -0.7213475204444817f);   // -0.5*log2e

    // carried state: pi, mu, r2s = -0.5*log2e/sigma^2, cf = C0/sigma^3
    u64 pi[Kn], mu[CKn], r2s[Kn], cf[Kn];
#pragma unroll
    for (int k = 0; k < Kn; k++) { pi[k] = pk(0.2f, 0.2f); r2s[k] = NHL2E2; cf[k] = C02; }
#pragma unroll
    for (int i = 0; i < CKn; i++) mu[i] = pk(m0[i * HWn], m1[i * HWn]);

    for (int s = 0; s < Sn; s++) {
        u64 x[Cn];
#pragma unroll
        for (int c = 0; c < Cn; c++)
            x[c] = pk(f0[(s * Cn + c) * HWn], f1[(s * Cn + c) * HWn]);

        // ---- density 1, alpha, rho ---------------------------------------
        u64 alpha[Kn], rho[Kn];
#pragma unroll
        for (int k = 0; k < Kn; k++) {
            u64 t0 = fma2(mu[k * Cn + 0], NEG12, x[0]);
            u64 d  = mul2(t0, t0);
            u64 t1 = fma2(mu[k * Cn + 1], NEG12, x[1]);
            d = fma2(t1, t1, d);
            u64 t2 = fma2(mu[k * Cn + 2], NEG12, x[2]);
            d = fma2(t2, t2, d);
            const u64 dens = mul2(cf[k], ex2_2(mul2(d, r2s[k])));
            alpha[k] = mul2(pi[k], dens);
            rho[k]   = mul2(alpha[k], dens);
        }

        // ---- pi MLP -> softmax (W2 pre-scaled by log2e) --------------------
        u64 hp[Kn];
#pragma unroll
        for (int o = 0; o < Kn; o++) {
            u64 a = cw2[PI_B1 + o];
#pragma unroll
            for (int i = 0; i < Kn; i++) a = fma2(cw2[PI_W1 + o * 10 + i],     pi[i],    a);
#pragma unroll
            for (int i = 0; i < Kn; i++) a = fma2(cw2[PI_W1 + o * 10 + 5 + i], alpha[i], a);
            hp[o] = relu2(a);
        }
        u64 pin[Kn], esum = 0ULL;
#pragma unroll
        for (int o = 0; o < Kn; o++) {
            u64 a = cw2[PI_B2 + o];
#pragma unroll
            for (int i = 0; i < Kn; i++) a = fma2(cw2[PI_W2 + o * 5 + i], hp[i], a);
            pin[o] = ex2_2(a);
            esum   = add2(esum, pin[o]);
        }
        {
            const u64 einv = rcp_2(esum);
#pragma unroll
            for (int k = 0; k < Kn; k++) pin[k] = mul2(pin[k], einv);
        }

        // ---- mu MLP -> sigmoid (W2 pre-scaled by -log2e) -------------------
        u64 hm[CKn];
#pragma unroll
        for (int o = 0; o < CKn; o++) {
            const int base = MU_W1 + o * 23;
            u64 a = cw2[MU_B1 + o];
#pragma unroll
            for (int c = 0; c < Cn; c++)  a = fma2(cw2[base + c],      x[c],   a);
#pragma unroll
            for (int i = 0; i < CKn; i++) a = fma2(cw2[base + 3 + i],  mu[i],  a);
#pragma unroll
            for (int i = 0; i < Kn; i++)  a = fma2(cw2[base + 18 + i], rho[i], a);
            hm[o] = relu2(a);
        }
        u64 mun[CKn];
#pragma unroll
        for (int o = 0; o < CKn; o++) {
            u64 a = cw2[MU_B2 + o];
#pragma unroll
            for (int i = 0; i < CKn; i++) a = fma2(cw2[MU_W2 + o * 15 + i], hm[i], a);
            mun[o] = rcp_2(add2(ex2_2(a), ONE2));   // sigmoid
        }

        // ---- sigma MLP (W2 pre-scaled by -log2e): rinv = ex2(min(a',0)) ----
        u64 hs[Kn];
#pragma unroll
        for (int o = 0; o < Kn; o++) {
            const int base = SG_W1 + o * 23;
            u64 a = cw2[SG_B1 + o];
#pragma unroll
            for (int c = 0; c < Cn; c++)  a = fma2(cw2[base + c],      x[c],   a);
#pragma unroll
            for (int i = 0; i < CKn; i++) a = fma2(cw2[base + 3 + i],  mun[i], a);
#pragma unroll
            for (int i = 0; i < Kn; i++)  a = fma2(cw2[base + 18 + i], rho[i], a);
            hs[o] = relu2(a);
        }
#pragma unroll
        for (int o = 0; o < Kn; o++) {
            u64 a = cw2[SG_B2 + o];
#pragma unroll
            for (int i = 0; i < Kn; i++) a = fma2(cw2[SG_W2 + o * 5 + i], hs[i], a);
            const u64 rin = ex2_2(min0_2(a));       // 1/sigma
            const u64 rr  = mul2(rin, rin);         // 1/sigma^2
            r2s[o] = mul2(rr, NHL2E2);
            cf[o]  = mul2(mul2(rin, C02), rr);      // C0/sigma^3
        }

        // ---- density 2, g = pi_new * dens2 ----------------------------------
        u64 g[Kn];
#pragma unroll
        for (int k = 0; k < Kn; k++) {
            u64 t0 = fma2(mun[k * Cn + 0], NEG12, x[0]);
            u64 d  = mul2(t0, t0);
            u64 t1 = fma2(mun[k * Cn + 1], NEG12, x[1]);
            d = fma2(t1, t1, d);
            u64 t2 = fma2(mun[k * Cn + 2], NEG12, x[2]);
            d = fma2(t2, t2, d);
            g[k] = mul2(pin[k], mul2(cf[k], ex2_2(mul2(d, r2s[k]))));
        }

        // ---- gamma MLP -> sigmoid (W2 pre-scaled by -log2e) -----------------
        u64 hg[Kn];
#pragma unroll
        for (int o = 0; o < Kn; o++) {
            u64 a = cw2[GA_B1 + o];
#pragma unroll
            for (int i = 0; i < Kn; i++) a = fma2(cw2[GA_W1 + o * 5 + i], g[i], a);
            hg[o] = relu2(a);
        }
        u64 ga = cw2[GA_B2];
#pragma unroll
        for (int i = 0; i < Kn; i++) ga = fma2(cw2[GA_W2 + i], hg[i], ga);
        {
            float al, ah; upk(ga, al, ah);
            o0[s * HWn] = rcpf(1.0f + ex2f(al));
            o1[s * HWn] = rcpf(1.0f + ex2f(ah));
        }

        // ---- carry -----------------------------------------------------------
#pragma unroll
        for (int k = 0; k < Kn; k++)  pi[k] = pin[k];
#pragma unroll
        for (int i = 0; i < CKn; i++) mu[i] = mun[i];
    }
}

extern "C" void kernel_launch(void* const* d_in, const int* in_sizes, int n_in,
                              void* d_out, int out_size)
{
    (void)in_sizes; (void)n_in; (void)out_size;
    const float* frames = (const float*)d_in[0];
    const float* mu0    = (const float*)d_in[2];   // d_in[1] = targets (unused)

    WPtrs w;
    for (int i = 0; i < 16; i++) w.p[i] = (const float*)d_in[3 + i];

    dup_weights<<<4, 256>>>(w);

    void* staging_addr = nullptr;
    cudaGetSymbolAddress(&staging_addr, g_staging);
    cudaMemcpyToSymbolAsync(cw2, staging_addr, NWTS * sizeof(u64), 0,
                            cudaMemcpyDeviceToDevice, 0);

    const int threads = 256;
    const int blocks  = HALF / threads;   // 1152
    gmm2_kernel<<<blocks, threads>>>(frames, mu0, (float*)d_out);
}